// round 2
// baseline (speedup 1.0000x reference)
#include <cuda_runtime.h>

#define LOG_FACTOR 3.4339872044851463f
#define HW    230400          // 480*480
#define HW4   57600           // HW/4
#define TDIM  20
#define NSLAB 40              // B*T
#define NACC  26
#define BLOCKS_PER_SLAB 15
#define THREADS 256

// Per-timestep accumulators:
// [0]=cnt [1]=Sp [2]=St [3]=Spt [4]=Spp [5]=Stt
// [6..10]=hits[l] [11..15]=p_tot[l] [16..20]=t_tot[l] [21..25]=mae_num[l]
__device__ double g_acc[TDIM * NACC];

__global__ void zero_kernel() {
    int i = threadIdx.x;
    if (i < TDIM * NACC) g_acc[i] = 0.0;
}

__device__ __forceinline__ int binidx(float v) {
    if (v < 0.1f) return -1;
    if (v < 1.0f) return 0;
    if (v < 2.0f) return 1;
    if (v < 5.0f) return 2;
    if (v < 8.0f) return 3;
    return 4;
}

__global__ __launch_bounds__(THREADS)
void accum_kernel(const float* __restrict__ pred,
                  const float* __restrict__ targ,
                  const float* __restrict__ mask) {
    const int s = blockIdx.y;           // slab in [0, 40): b = s/20, t = s%20
    const int t = s % TDIM;
    const float4* P = reinterpret_cast<const float4*>(pred) + (size_t)s * HW4;
    const float4* Q = reinterpret_cast<const float4*>(targ) + (size_t)s * HW4;
    const float4* M = reinterpret_cast<const float4*>(mask) + (size_t)s * HW4;

    float cnt = 0.f, sp = 0.f, st = 0.f, spt = 0.f, spp = 0.f, stt = 0.f;
    int   hits[5] = {0,0,0,0,0};
    int   ptot[5] = {0,0,0,0,0};
    int   ttot[5] = {0,0,0,0,0};
    float mae[5]  = {0.f,0.f,0.f,0.f,0.f};

#define PROC(PN, QN, MV) do {                                            \
        float p = __expf((PN) * LOG_FACTOR) - 1.0f; p = fmaxf(p, 0.0f);  \
        float q = __expf((QN) * LOG_FACTOR) - 1.0f; q = fmaxf(q, 0.0f);  \
        bool  m = (MV) > 0.5f;                                           \
        int lp = binidx(p), lq = binidx(q);                              \
        if (m && (lp >= 0 || lq >= 0)) {                                 \
            cnt += 1.f; sp += p; st += q;                                \
            spt = fmaf(p, q, spt); spp = fmaf(p, p, spp);                \
            stt = fmaf(q, q, stt);                                       \
        }                                                                \
        float d = fabsf(p - q);                                          \
        _Pragma("unroll")                                                \
        for (int l = 0; l < 5; l++) {                                    \
            bool pi = m && (lp == l);                                    \
            bool ti = m && (lq == l);                                    \
            ptot[l] += pi ? 1 : 0;                                       \
            ttot[l] += ti ? 1 : 0;                                       \
            hits[l] += (pi && ti) ? 1 : 0;                               \
            mae[l]  += ti ? d : 0.0f;                                    \
        }                                                                \
    } while (0)

    for (int i = blockIdx.x * blockDim.x + threadIdx.x; i < HW4;
         i += blockDim.x * gridDim.x) {
        float4 pv = P[i];
        float4 qv = Q[i];
        float4 mv = M[i];
        PROC(pv.x, qv.x, mv.x);
        PROC(pv.y, qv.y, mv.y);
        PROC(pv.z, qv.z, mv.z);
        PROC(pv.w, qv.w, mv.w);
    }
#undef PROC

    // Pack all 26 accumulators as float (counts <= 60/thread, exact in fp32).
    float a[NACC];
    a[0] = cnt; a[1] = sp; a[2] = st; a[3] = spt; a[4] = spp; a[5] = stt;
#pragma unroll
    for (int l = 0; l < 5; l++) {
        a[6 + l]  = (float)hits[l];
        a[11 + l] = (float)ptot[l];
        a[16 + l] = (float)ttot[l];
        a[21 + l] = mae[l];
    }

    // Warp-level reduce each accumulator.
#pragma unroll
    for (int j = 0; j < NACC; j++) {
#pragma unroll
        for (int off = 16; off; off >>= 1)
            a[j] += __shfl_down_sync(0xffffffffu, a[j], off);
    }

    __shared__ float sred[THREADS / 32][NACC];
    const int wid  = threadIdx.x >> 5;
    const int lane = threadIdx.x & 31;
    if (lane == 0) {
#pragma unroll
        for (int j = 0; j < NACC; j++) sred[wid][j] = a[j];
    }
    __syncthreads();

    if (threadIdx.x < NACC) {
        float v = 0.f;
#pragma unroll
        for (int w = 0; w < THREADS / 32; w++) v += sred[w][threadIdx.x];
        atomicAdd(&g_acc[t * NACC + threadIdx.x], (double)v);
    }
}

__global__ void finalize_kernel(float* __restrict__ out, int out_size) {
    __shared__ float s_score[TDIM];
    __shared__ float s_ts[TDIM][5];
    __shared__ float s_mae[TDIM][5];

    const float LW[5] = {0.1f, 0.1f, 0.2f, 0.25f, 0.35f};
    const float TW[TDIM] = {0.0075f, 0.02f, 0.03f, 0.04f, 0.05f, 0.06f, 0.07f,
                            0.08f, 0.09f, 0.1f, 0.09f, 0.08f, 0.07f, 0.06f,
                            0.05f, 0.04f, 0.03f, 0.02f, 0.0075f, 0.005f};

#define PUT(IDX, V) do { int _i = (IDX); if (_i < out_size) out[_i] = (V); } while (0)

    const int t = threadIdx.x;
    if (t < TDIM) {
        const double* A = &g_acc[t * NACC];
        double cnt = A[0];
        double ic  = 1.0 / fmax(cnt, 1.0);
        double num = A[3] - A[1] * A[2] * ic;
        double vp  = fmax(A[4] - A[1] * A[1] * ic, 0.0);
        double vt  = fmax(A[5] - A[2] * A[2] * ic, 0.0);
        double den = sqrt(vp * vt);
        float r = 0.f;
        if (cnt > 0.0) {
            double rr = num / (den + 1e-6);
            rr = fmin(fmax(rr, -1.0), 1.0);
            r = (float)rr;
        }
        PUT(21 + t, r);

        float term_corr = sqrtf(expf(r - 1.0f));
        float sc = 0.f;
#pragma unroll
        for (int l = 0; l < 5; l++) {
            float h  = (float)A[6 + l];
            float pt = (float)A[11 + l];
            float tt = (float)A[16 + l];
            float mn = (float)A[21 + l];
            float ts  = h / (pt + tt - h + 1e-8f);
            float mmv = (tt > 0.f) ? (mn / fmaxf(tt, 1.f)) : 0.f;
            PUT(41  + t * 5 + l, ts);
            PUT(141 + t * 5 + l, mmv);
            s_ts[t][l]  = ts;
            s_mae[t][l] = mmv;
            sc += LW[l] * ts * sqrtf(expf(-mmv / 100.0f));
        }
        sc *= term_corr;
        PUT(1 + t, sc);
        s_score[t] = sc;
    }
    __syncthreads();

    if (threadIdx.x == 0) {
        float total = 0.f;
        for (int tt = 0; tt < TDIM; tt++) total += s_score[tt] * TW[tt];
        PUT(0, total);
        for (int l = 0; l < 5; l++) {
            float am = 0.f, bm = 0.f;
            for (int tt = 0; tt < TDIM; tt++) { am += s_ts[tt][l]; bm += s_mae[tt][l]; }
            PUT(241 + l, am / (float)TDIM);
            PUT(246 + l, bm / (float)TDIM);
        }
    }
#undef PUT

    // Zero any padding beyond the 251 defined outputs.
    for (int i = 251 + threadIdx.x; i < out_size; i += blockDim.x) out[i] = 0.f;
}

extern "C" void kernel_launch(void* const* d_in, const int* in_sizes, int n_in,
                              void* d_out, int out_size) {
    const float* pred = (const float*)d_in[0];
    const float* targ = (const float*)d_in[1];
    const float* mask = (const float*)d_in[2];

    zero_kernel<<<1, 544>>>();
    dim3 grid(BLOCKS_PER_SLAB, NSLAB);
    accum_kernel<<<grid, THREADS>>>(pred, targ, mask);
    finalize_kernel<<<1, 64>>>((float*)d_out, out_size);
}